// round 11
// baseline (speedup 1.0000x reference)
#include <cuda_runtime.h>
#include <cstdint>

// out[b, t, h] = sum_{j=0..4} x[b, t+j, h] * a[b, t+j]
// x: (32,1,2052,768) f32, a: (32,2052) f32, out: (32,1,2048,768) f32
//
// R11 = R10 (bulk-DMA in/out, register sliding window, TT=64, grid 1024,
//       2 CTA/SM, IN5 ring of 12KB chunks, split loader/storer warps)
//     + 24KB store bursts: two compute chunks accumulate into one 24KB out
//       stage, one bulk store per pair. Longer same-direction write bursts
//       => fewer MC read/write turnarounds.

constexpr int LENGTH = 2048;
constexpr int H      = 768;
constexpr int PAD    = LENGTH + 4;           // 2052
constexpr int ROWB   = H * 4;                // 3072 B per row
constexpr int H4     = H / 4;                // 192
constexpr int TT     = 64;                   // output rows per CTA
constexpr int CR     = 4;                    // rows per load chunk
constexpr int CHUNK  = CR * ROWB;            // 12288 B
constexpr int OUTCHUNK = 2 * CHUNK;          // 24576 B (8 rows per store)
constexpr int NCH    = TT / CR;              // 16 compute chunks
constexpr int NPAIR  = NCH / 2;              // 8 store pairs
constexpr int NIN    = NCH + 1;              // 17 input chunks
constexpr int IN_STAGES  = 5;
constexpr int OUT_STAGES = 2;                // 2 x 24KB
constexpr int B      = 32;
constexpr int THREADS = H4;                  // 192

constexpr int MBAR_OFF = 0;                              // 5 mbarriers * 8B
constexpr int WA_OFF   = 64;                             // 68 floats
constexpr int IN_OFF   = 512;
constexpr int OUT_OFF  = IN_OFF + IN_STAGES * CHUNK;     // 61952
constexpr int SMEM_TOTAL = OUT_OFF + OUT_STAGES * OUTCHUNK; // 111104

__device__ __forceinline__ uint32_t smem_u32(const void* p) {
    return (uint32_t)__cvta_generic_to_shared(p);
}
__device__ __forceinline__ void mbar_init(uint32_t bar, uint32_t count) {
    asm volatile("mbarrier.init.shared.b64 [%0], %1;" :: "r"(bar), "r"(count) : "memory");
}
__device__ __forceinline__ void mbar_expect_tx(uint32_t bar, uint32_t bytes) {
    asm volatile("mbarrier.arrive.expect_tx.shared.b64 _, [%0], %1;"
                 :: "r"(bar), "r"(bytes) : "memory");
}
__device__ __forceinline__ void mbar_wait(uint32_t bar, uint32_t parity) {
    uint32_t done;
    asm volatile(
        "{\n\t.reg .pred p;\n\t"
        "mbarrier.try_wait.parity.acquire.cta.shared::cta.b64 p, [%1], %2;\n\t"
        "selp.b32 %0, 1, 0, p;\n\t}"
        : "=r"(done) : "r"(bar), "r"(parity) : "memory");
    if (!done) {
        asm volatile(
            "{\n\t.reg .pred P1;\n\t"
            "W_%=:\n\t"
            "mbarrier.try_wait.parity.acquire.cta.shared::cta.b64 P1, [%0], %1, 0x989680;\n\t"
            "@P1 bra.uni D_%=;\n\t"
            "bra.uni W_%=;\n\t"
            "D_%=:\n\t}"
            :: "r"(bar), "r"(parity) : "memory");
    }
}
__device__ __forceinline__ void bulk_g2s(uint32_t dst_smem, const void* src_gmem,
                                         uint32_t bytes, uint32_t bar) {
    asm volatile(
        "cp.async.bulk.shared::cluster.global.mbarrier::complete_tx::bytes "
        "[%0], [%1], %2, [%3];"
        :: "r"(dst_smem), "l"(src_gmem), "r"(bytes), "r"(bar) : "memory");
}
__device__ __forceinline__ void bulk_s2g(void* dst_gmem, uint32_t src_smem,
                                         uint32_t bytes) {
    asm volatile(
        "cp.async.bulk.global.shared::cta.bulk_group [%0], [%1], %2;"
        :: "l"(dst_gmem), "r"(src_smem), "r"(bytes) : "memory");
}

__global__ __launch_bounds__(THREADS, 2) void widthap_kernel(
    const float* __restrict__ x,
    const float* __restrict__ att,
    float* __restrict__ out)
{
    extern __shared__ char smem[];
    const int tid = threadIdx.x;     // 0..191 = float4 column
    const int b   = blockIdx.y;
    const int t0  = blockIdx.x * TT;

    uint32_t sbase = smem_u32(smem);
    uint32_t mbar  = sbase + MBAR_OFF;

    float* wa = reinterpret_cast<float*>(smem + WA_OFF);
    if (tid < TT + 4)   // 68 weights
        wa[tid] = att[b * PAD + t0 + tid];

    if (tid == 0) {
        #pragma unroll
        for (int s = 0; s < IN_STAGES; s++)
            mbar_init(mbar + s * 8, 1);
    }
    __syncthreads();

    const char* xsrc = reinterpret_cast<const char*>(x) +
                       ((size_t)b * PAD + t0) * ROWB;
    char* odst = reinterpret_cast<char*>(out) +
                 ((size_t)b * LENGTH + t0) * ROWB;

    // prime input chunks 0..4 (loader warp: tid 0)
    if (tid == 0) {
        #pragma unroll
        for (int ci = 0; ci < IN_STAGES; ci++) {
            mbar_expect_tx(mbar + ci * 8, CHUNK);
            bulk_g2s(sbase + IN_OFF + ci * CHUNK,
                     xsrc + (size_t)ci * CHUNK, CHUNK, mbar + ci * 8);
        }
    }

    // Prologue: consume chunk 0 into the register window (rows 0..3, weighted)
    float4 w0, w1, w2, w3;
    {
        mbar_wait(mbar + 0, 0);
        const float4* in0 = reinterpret_cast<const float4*>(smem + IN_OFF);
        float4 v;
        v = in0[0 * H4 + tid]; w0 = make_float4(v.x*wa[0], v.y*wa[0], v.z*wa[0], v.w*wa[0]);
        v = in0[1 * H4 + tid]; w1 = make_float4(v.x*wa[1], v.y*wa[1], v.z*wa[1], v.w*wa[1]);
        v = in0[2 * H4 + tid]; w2 = make_float4(v.x*wa[2], v.y*wa[2], v.z*wa[2], v.w*wa[2]);
        v = in0[3 * H4 + tid]; w3 = make_float4(v.x*wa[3], v.y*wa[3], v.z*wa[3], v.w*wa[3]);
    }

    for (int co = 0; co < NCH; co++) {
        // (a) storer warp, at each pair start: drain ALL outstanding stores
        //     (only pair co/2-2 can still be in flight -> frees its stage).
        if (tid == 64 && (co & 1) == 0 && co >= 4)
            asm volatile("cp.async.bulk.wait_group.read 0;" ::: "memory");

        // (b) one barrier: prev iter's LDS+STS retired; (a) visible to all
        __syncthreads();

        // (c1) storer warp: at pair start, store the completed previous pair
        if (tid == 64 && (co & 1) == 0 && co >= 2) {
            int p = co / 2 - 1;     // completed pair (chunks 2p, 2p+1)
            asm volatile("fence.proxy.async.shared::cta;" ::: "memory");
            bulk_s2g(odst + (size_t)p * OUTCHUNK,
                     sbase + OUT_OFF + (p & 1) * OUTCHUNK, OUTCHUNK);
            asm volatile("cp.async.bulk.commit_group;" ::: "memory");
        }
        // (c2) loader warp: refill the input stage freed in (b)
        if (tid == 0) {
            int ci = co + IN_STAGES;
            if (ci < NIN) {
                int s = ci % IN_STAGES;
                mbar_expect_tx(mbar + s * 8, CHUNK);
                bulk_g2s(sbase + IN_OFF + s * CHUNK,
                         xsrc + (size_t)ci * CHUNK, CHUNK, mbar + s * 8);
            }
        }

        // (d) consume input chunk co+1 (single read of each smem byte)
        const int ci = co + 1;
        mbar_wait(mbar + (ci % IN_STAGES) * 8, (ci / IN_STAGES) & 1);

        const float4* in = reinterpret_cast<const float4*>(
            smem + IN_OFF + (ci % IN_STAGES) * CHUNK);
        const int wb = 4 * co + 4;
        float4 n0, n1, n2, n3, v;
        v = in[0 * H4 + tid]; { float a = wa[wb+0]; n0 = make_float4(v.x*a, v.y*a, v.z*a, v.w*a); }
        v = in[1 * H4 + tid]; { float a = wa[wb+1]; n1 = make_float4(v.x*a, v.y*a, v.z*a, v.w*a); }
        v = in[2 * H4 + tid]; { float a = wa[wb+2]; n2 = make_float4(v.x*a, v.y*a, v.z*a, v.w*a); }
        v = in[3 * H4 + tid]; { float a = wa[wb+3]; n3 = make_float4(v.x*a, v.y*a, v.z*a, v.w*a); }

        // out stage: pair (co>>1) & 1, half (co & 1)
        float4* os = reinterpret_cast<float4*>(
            smem + OUT_OFF + ((co >> 1) & 1) * OUTCHUNK + (co & 1) * CHUNK);
        float4 s;
        s.x = w0.x+w1.x+w2.x+w3.x+n0.x; s.y = w0.y+w1.y+w2.y+w3.y+n0.y;
        s.z = w0.z+w1.z+w2.z+w3.z+n0.z; s.w = w0.w+w1.w+w2.w+w3.w+n0.w;
        os[0 * H4 + tid] = s;
        s.x = w1.x+w2.x+w3.x+n0.x+n1.x; s.y = w1.y+w2.y+w3.y+n0.y+n1.y;
        s.z = w1.z+w2.z+w3.z+n0.z+n1.z; s.w = w1.w+w2.w+w3.w+n0.w+n1.w;
        os[1 * H4 + tid] = s;
        s.x = w2.x+w3.x+n0.x+n1.x+n2.x; s.y = w2.y+w3.y+n0.y+n1.y+n2.y;
        s.z = w2.z+w3.z+n0.z+n1.z+n2.z; s.w = w2.w+w3.w+n0.w+n1.w+n2.w;
        os[2 * H4 + tid] = s;
        s.x = w3.x+n0.x+n1.x+n2.x+n3.x; s.y = w3.y+n0.y+n1.y+n2.y+n3.y;
        s.z = w3.z+n0.z+n1.z+n2.z+n3.z; s.w = w3.w+n0.w+n1.w+n2.w+n3.w;
        os[3 * H4 + tid] = s;

        w0 = n0; w1 = n1; w2 = n2; w3 = n3;
    }

    // Epilogue: store the final pair (NPAIR-1)
    __syncthreads();
    if (tid == 64) {
        int p = NPAIR - 1;
        asm volatile("fence.proxy.async.shared::cta;" ::: "memory");
        bulk_s2g(odst + (size_t)p * OUTCHUNK,
                 sbase + OUT_OFF + (p & 1) * OUTCHUNK, OUTCHUNK);
        asm volatile("cp.async.bulk.commit_group;" ::: "memory");
        asm volatile("cp.async.bulk.wait_group.read 0;" ::: "memory");
    }
}

extern "C" void kernel_launch(void* const* d_in, const int* in_sizes, int n_in,
                              void* d_out, int out_size)
{
    const float* x   = (const float*)d_in[0];   // (32,1,2052,768)
    const float* att = (const float*)d_in[1];   // (32,2052)
    float* out       = (float*)d_out;           // (32,1,2048,768)

    cudaFuncSetAttribute(widthap_kernel,
                         cudaFuncAttributeMaxDynamicSharedMemorySize, SMEM_TOTAL);

    dim3 grid(LENGTH / TT, B);   // (32, 32) = 1024 CTAs
    dim3 block(THREADS);         // 192
    widthap_kernel<<<grid, block, SMEM_TOTAL>>>(x, att, out);
}

// round 12
// speedup vs baseline: 1.0232x; 1.0232x over previous
#include <cuda_runtime.h>
#include <cstdint>

// out[b, t, h] = sum_{j=0..4} x[b, t+j, h] * a[b, t+j]
// x: (32,1,2052,768) f32, a: (32,2052) f32, out: (32,1,2048,768) f32
//
// FINAL (R10 config, confirmed best): bulk-DMA in/out pipeline with a
// column-persistent register sliding window.
//   - Each CTA owns (batch b, 64 output rows); 192 threads each own one
//     float4 column for the whole tile.
//   - Input rows stream gmem->smem as 12KB cp.async.bulk chunks through a
//     5-stage mbarrier ring; outputs accumulate in a 3-stage smem ring and
//     leave via 12KB cp.async.bulk stores. Every DRAM byte crosses smem
//     exactly twice; every smem input byte is LDS-read exactly once.
//   - Split DMA duties: tid 0 issues input loads, tid 64 issues output
//     stores + drain waits (per-thread bulk_group state keeps this legal).
//   - One __syncthreads + one mbar-wait per chunk.
// Measured: ~67.5us wall, 75% DRAM (5.95 TB/s) — at the sustained mixed
// 1:1 R/W HBM efficiency ceiling for this chip (plateau confirmed over 11
// structural variants).

constexpr int LENGTH = 2048;
constexpr int H      = 768;
constexpr int PAD    = LENGTH + 4;           // 2052
constexpr int ROWB   = H * 4;                // 3072 B per row
constexpr int H4     = H / 4;                // 192
constexpr int TT     = 64;                   // output rows per CTA
constexpr int CR     = 4;                    // rows per chunk
constexpr int CHUNK  = CR * ROWB;            // 12288 B
constexpr int NCH    = TT / CR;              // 16 output chunks
constexpr int NIN    = NCH + 1;              // 17 input chunks
constexpr int IN_STAGES  = 5;
constexpr int OUT_STAGES = 3;
constexpr int B      = 32;
constexpr int THREADS = H4;                  // 192

constexpr int MBAR_OFF = 0;                              // 5 mbarriers * 8B
constexpr int WA_OFF   = 64;                             // 68 floats
constexpr int IN_OFF   = 512;
constexpr int OUT_OFF  = IN_OFF + IN_STAGES * CHUNK;     // 61952
constexpr int SMEM_TOTAL = OUT_OFF + OUT_STAGES * CHUNK; // 98816

__device__ __forceinline__ uint32_t smem_u32(const void* p) {
    return (uint32_t)__cvta_generic_to_shared(p);
}
__device__ __forceinline__ void mbar_init(uint32_t bar, uint32_t count) {
    asm volatile("mbarrier.init.shared.b64 [%0], %1;" :: "r"(bar), "r"(count) : "memory");
}
__device__ __forceinline__ void mbar_expect_tx(uint32_t bar, uint32_t bytes) {
    asm volatile("mbarrier.arrive.expect_tx.shared.b64 _, [%0], %1;"
                 :: "r"(bar), "r"(bytes) : "memory");
}
__device__ __forceinline__ void mbar_wait(uint32_t bar, uint32_t parity) {
    uint32_t done;
    asm volatile(
        "{\n\t.reg .pred p;\n\t"
        "mbarrier.try_wait.parity.acquire.cta.shared::cta.b64 p, [%1], %2;\n\t"
        "selp.b32 %0, 1, 0, p;\n\t}"
        : "=r"(done) : "r"(bar), "r"(parity) : "memory");
    if (!done) {
        asm volatile(
            "{\n\t.reg .pred P1;\n\t"
            "W_%=:\n\t"
            "mbarrier.try_wait.parity.acquire.cta.shared::cta.b64 P1, [%0], %1, 0x989680;\n\t"
            "@P1 bra.uni D_%=;\n\t"
            "bra.uni W_%=;\n\t"
            "D_%=:\n\t}"
            :: "r"(bar), "r"(parity) : "memory");
    }
}
__device__ __forceinline__ void bulk_g2s(uint32_t dst_smem, const void* src_gmem,
                                         uint32_t bytes, uint32_t bar) {
    asm volatile(
        "cp.async.bulk.shared::cluster.global.mbarrier::complete_tx::bytes "
        "[%0], [%1], %2, [%3];"
        :: "r"(dst_smem), "l"(src_gmem), "r"(bytes), "r"(bar) : "memory");
}
__device__ __forceinline__ void bulk_s2g(void* dst_gmem, uint32_t src_smem,
                                         uint32_t bytes) {
    asm volatile(
        "cp.async.bulk.global.shared::cta.bulk_group [%0], [%1], %2;"
        :: "l"(dst_gmem), "r"(src_smem), "r"(bytes) : "memory");
}

__global__ __launch_bounds__(THREADS, 2) void widthap_kernel(
    const float* __restrict__ x,
    const float* __restrict__ att,
    float* __restrict__ out)
{
    extern __shared__ char smem[];
    const int tid = threadIdx.x;     // 0..191 = float4 column
    const int b   = blockIdx.y;
    const int t0  = blockIdx.x * TT;

    uint32_t sbase = smem_u32(smem);
    uint32_t mbar  = sbase + MBAR_OFF;

    float* wa = reinterpret_cast<float*>(smem + WA_OFF);
    if (tid < TT + 4)   // 68 weights
        wa[tid] = att[b * PAD + t0 + tid];

    if (tid == 0) {
        #pragma unroll
        for (int s = 0; s < IN_STAGES; s++)
            mbar_init(mbar + s * 8, 1);
    }
    __syncthreads();

    const char* xsrc = reinterpret_cast<const char*>(x) +
                       ((size_t)b * PAD + t0) * ROWB;
    char* odst = reinterpret_cast<char*>(out) +
                 ((size_t)b * LENGTH + t0) * ROWB;

    // prime input chunks 0..4 into stages 0..4 (loader warp: tid 0)
    if (tid == 0) {
        #pragma unroll
        for (int ci = 0; ci < IN_STAGES; ci++) {
            mbar_expect_tx(mbar + ci * 8, CHUNK);
            bulk_g2s(sbase + IN_OFF + ci * CHUNK,
                     xsrc + (size_t)ci * CHUNK, CHUNK, mbar + ci * 8);
        }
    }

    // Prologue: consume chunk 0 into the register window (rows 0..3, weighted)
    float4 w0, w1, w2, w3;
    {
        mbar_wait(mbar + 0, 0);
        const float4* in0 = reinterpret_cast<const float4*>(smem + IN_OFF);
        float4 v;
        v = in0[0 * H4 + tid]; w0 = make_float4(v.x*wa[0], v.y*wa[0], v.z*wa[0], v.w*wa[0]);
        v = in0[1 * H4 + tid]; w1 = make_float4(v.x*wa[1], v.y*wa[1], v.z*wa[1], v.w*wa[1]);
        v = in0[2 * H4 + tid]; w2 = make_float4(v.x*wa[2], v.y*wa[2], v.z*wa[2], v.w*wa[2]);
        v = in0[3 * H4 + tid]; w3 = make_float4(v.x*wa[3], v.y*wa[3], v.z*wa[3], v.w*wa[3]);
    }

    for (int co = 0; co < NCH; co++) {
        // (a) storer warp: free the oldest out-stage before STS reuse.
        if (tid == 64 && co >= 2)
            asm volatile("cp.async.bulk.wait_group.read 1;" ::: "memory");

        // (b) one barrier: prev iter's LDS+STS done; out-stage drain visible
        __syncthreads();

        // (c1) storer warp (tid 64): store prev output chunk
        if (tid == 64 && co >= 1) {
            asm volatile("fence.proxy.async.shared::cta;" ::: "memory");
            bulk_s2g(odst + (size_t)(co - 1) * CHUNK,
                     sbase + OUT_OFF + ((co - 1) % OUT_STAGES) * CHUNK, CHUNK);
            asm volatile("cp.async.bulk.commit_group;" ::: "memory");
        }
        // (c2) loader warp (tid 0): refill the input stage freed in (b)
        if (tid == 0) {
            int ci = co + IN_STAGES;
            if (ci < NIN) {
                int s = ci % IN_STAGES;
                mbar_expect_tx(mbar + s * 8, CHUNK);
                bulk_g2s(sbase + IN_OFF + s * CHUNK,
                         xsrc + (size_t)ci * CHUNK, CHUNK, mbar + s * 8);
            }
        }

        // (d) consume input chunk co+1 (single read of each smem byte)
        const int ci = co + 1;
        mbar_wait(mbar + (ci % IN_STAGES) * 8, (ci / IN_STAGES) & 1);

        const float4* in = reinterpret_cast<const float4*>(
            smem + IN_OFF + (ci % IN_STAGES) * CHUNK);
        const int wb = 4 * co + 4;   // weight index of first new row
        float4 n0, n1, n2, n3, v;
        v = in[0 * H4 + tid]; { float a = wa[wb+0]; n0 = make_float4(v.x*a, v.y*a, v.z*a, v.w*a); }
        v = in[1 * H4 + tid]; { float a = wa[wb+1]; n1 = make_float4(v.x*a, v.y*a, v.z*a, v.w*a); }
        v = in[2 * H4 + tid]; { float a = wa[wb+2]; n2 = make_float4(v.x*a, v.y*a, v.z*a, v.w*a); }
        v = in[3 * H4 + tid]; { float a = wa[wb+3]; n3 = make_float4(v.x*a, v.y*a, v.z*a, v.w*a); }

        float4* os = reinterpret_cast<float4*>(
            smem + OUT_OFF + (co % OUT_STAGES) * CHUNK);
        float4 s;
        s.x = w0.x+w1.x+w2.x+w3.x+n0.x; s.y = w0.y+w1.y+w2.y+w3.y+n0.y;
        s.z = w0.z+w1.z+w2.z+w3.z+n0.z; s.w = w0.w+w1.w+w2.w+w3.w+n0.w;
        os[0 * H4 + tid] = s;
        s.x = w1.x+w2.x+w3.x+n0.x+n1.x; s.y = w1.y+w2.y+w3.y+n0.y+n1.y;
        s.z = w1.z+w2.z+w3.z+n0.z+n1.z; s.w = w1.w+w2.w+w3.w+n0.w+n1.w;
        os[1 * H4 + tid] = s;
        s.x = w2.x+w3.x+n0.x+n1.x+n2.x; s.y = w2.y+w3.y+n0.y+n1.y+n2.y;
        s.z = w2.z+w3.z+n0.z+n1.z+n2.z; s.w = w2.w+w3.w+n0.w+n1.w+n2.w;
        os[2 * H4 + tid] = s;
        s.x = w3.x+n0.x+n1.x+n2.x+n3.x; s.y = w3.y+n0.y+n1.y+n2.y+n3.y;
        s.z = w3.z+n0.z+n1.z+n2.z+n3.z; s.w = w3.w+n0.w+n1.w+n2.w+n3.w;
        os[3 * H4 + tid] = s;

        w0 = n0; w1 = n1; w2 = n2; w3 = n3;
    }

    // Epilogue: store last output chunk (storer warp)
    __syncthreads();
    if (tid == 64) {
        asm volatile("fence.proxy.async.shared::cta;" ::: "memory");
        bulk_s2g(odst + (size_t)(NCH - 1) * CHUNK,
                 sbase + OUT_OFF + ((NCH - 1) % OUT_STAGES) * CHUNK, CHUNK);
        asm volatile("cp.async.bulk.commit_group;" ::: "memory");
        asm volatile("cp.async.bulk.wait_group.read 0;" ::: "memory");
    }
}

extern "C" void kernel_launch(void* const* d_in, const int* in_sizes, int n_in,
                              void* d_out, int out_size)
{
    const float* x   = (const float*)d_in[0];   // (32,1,2052,768)
    const float* att = (const float*)d_in[1];   // (32,2052)
    float* out       = (float*)d_out;           // (32,1,2048,768)

    cudaFuncSetAttribute(widthap_kernel,
                         cudaFuncAttributeMaxDynamicSharedMemorySize, SMEM_TOTAL);

    dim3 grid(LENGTH / TT, B);   // (32, 32) = 1024 CTAs
    dim3 block(THREADS);         // 192
    widthap_kernel<<<grid, block, SMEM_TOTAL>>>(x, att, out);
}